// round 1
// baseline (speedup 1.0000x reference)
#include <cuda_runtime.h>
#include <math.h>
#include <stdint.h>

#define NN 50000
#define EE 1600000
#define D 128
#define DAGG 384
#define AVG_D_LOG_F 3.4965075614664802f

// ---------------- scratch (static device globals; no runtime allocation) ----
__device__ int g_deg[NN];
__device__ int g_off[NN + 1];
__device__ int g_cur[NN];
__device__ int g_srcl[EE];
__device__ float g_wl[EE];
__device__ __align__(16) float g_agg[(size_t)NN * DAGG];   // [N,384] fp32
__device__ __align__(16) float g_Y[(size_t)NN * DAGG];     // [N,384] fp32

// ---------------- helpers ---------------------------------------------------
__device__ __forceinline__ uint32_t f2tf32(float f) {
    uint32_t r;
    asm("cvt.rna.tf32.f32 %0, %1;" : "=r"(r) : "f"(f));
    return r;
}

__device__ __forceinline__ void mma_tf32(float* c, const uint32_t* a,
                                         uint32_t b0, uint32_t b1) {
    asm volatile(
        "mma.sync.aligned.m16n8k8.row.col.f32.tf32.tf32.f32 "
        "{%0,%1,%2,%3}, {%4,%5,%6,%7}, {%8,%9}, {%0,%1,%2,%3};\n"
        : "+f"(c[0]), "+f"(c[1]), "+f"(c[2]), "+f"(c[3])
        : "r"(a[0]), "r"(a[1]), "r"(a[2]), "r"(a[3]), "r"(b0), "r"(b1));
}

// ---------------- kernel 1: zero degree -------------------------------------
__global__ void k_init() {
    int i = blockIdx.x * blockDim.x + threadIdx.x;
    if (i < NN) g_deg[i] = 0;
}

// ---------------- kernel 2: degree count ------------------------------------
__global__ void k_deg(const int* __restrict__ dst) {
    int i = blockIdx.x * blockDim.x + threadIdx.x;
    if (i < EE) atomicAdd(&g_deg[dst[i]], 1);
}

// ---------------- kernel 3: exclusive scan (single block) -------------------
__global__ void k_scan() {
    __shared__ int sm[1024];
    int tid = threadIdx.x;
    int running = 0;
    for (int base = 0; base < NN; base += 1024) {
        int i = base + tid;
        int v = (i < NN) ? g_deg[i] : 0;
        sm[tid] = v;
        __syncthreads();
        for (int off = 1; off < 1024; off <<= 1) {
            int t = (tid >= off) ? sm[tid - off] : 0;
            __syncthreads();
            sm[tid] += t;
            __syncthreads();
        }
        int incl = sm[tid];
        int total = sm[1023];
        if (i < NN) {
            int ex = running + incl - v;
            g_off[i] = ex;
            g_cur[i] = ex;
        }
        running += total;
        __syncthreads();
    }
    if (tid == 0) g_off[NN] = running;
}

// ---------------- kernel 4: CSR fill (src index + dir1 weight) --------------
__global__ void k_fill(const int* __restrict__ src, const int* __restrict__ dst,
                       const float* __restrict__ eig) {
    int i = blockIdx.x * blockDim.x + threadIdx.x;
    if (i >= EE) return;
    int s = src[i];
    int d = dst[i];
    int pos = atomicAdd(&g_cur[d], 1);
    g_srcl[pos] = s;
    g_wl[pos] = fabsf(eig[(size_t)s * 4] - eig[(size_t)d * 4]);
}

// ---------------- kernel 5: warp-per-node multi-aggregator reduce -----------
__global__ __launch_bounds__(256) void k_reduce(const float4* __restrict__ h4) {
    int wid = threadIdx.x >> 5;
    int lane = threadIdx.x & 31;
    int node = blockIdx.x * 8 + wid;
    if (node >= NN) return;
    int beg = g_off[node];
    int end = g_off[node + 1];

    float sx = 0.f, sy = 0.f, sz = 0.f, sw = 0.f;
    float mxx = -3.402823466e38f, mxy = mxx, mxz = mxx, mxw = mxx;
    float dx = 0.f, dy = 0.f, dz = 0.f, dw = 0.f;
    float wsum = 0.f;

    int j = beg;
    for (; j + 2 <= end; j += 2) {
        int s0 = g_srcl[j];
        int s1 = g_srcl[j + 1];
        float w0 = g_wl[j];
        float w1 = g_wl[j + 1];
        float4 v0 = h4[(size_t)s0 * 32 + lane];
        float4 v1 = h4[(size_t)s1 * 32 + lane];
        sx += v0.x; sy += v0.y; sz += v0.z; sw += v0.w;
        mxx = fmaxf(mxx, v0.x); mxy = fmaxf(mxy, v0.y);
        mxz = fmaxf(mxz, v0.z); mxw = fmaxf(mxw, v0.w);
        dx = fmaf(w0, v0.x, dx); dy = fmaf(w0, v0.y, dy);
        dz = fmaf(w0, v0.z, dz); dw = fmaf(w0, v0.w, dw);
        wsum += w0;
        sx += v1.x; sy += v1.y; sz += v1.z; sw += v1.w;
        mxx = fmaxf(mxx, v1.x); mxy = fmaxf(mxy, v1.y);
        mxz = fmaxf(mxz, v1.z); mxw = fmaxf(mxw, v1.w);
        dx = fmaf(w1, v1.x, dx); dy = fmaf(w1, v1.y, dy);
        dz = fmaf(w1, v1.z, dz); dw = fmaf(w1, v1.w, dw);
        wsum += w1;
    }
    if (j < end) {
        int s0 = g_srcl[j];
        float w0 = g_wl[j];
        float4 v0 = h4[(size_t)s0 * 32 + lane];
        sx += v0.x; sy += v0.y; sz += v0.z; sw += v0.w;
        mxx = fmaxf(mxx, v0.x); mxy = fmaxf(mxy, v0.y);
        mxz = fmaxf(mxz, v0.z); mxw = fmaxf(mxw, v0.w);
        dx = fmaf(w0, v0.x, dx); dy = fmaf(w0, v0.y, dy);
        dz = fmaf(w0, v0.z, dz); dw = fmaf(w0, v0.w, dw);
        wsum += w0;
    }

    int deg = end - beg;
    float invd = 1.f / (float)(deg > 0 ? deg : 1);
    float invw = 1.f / (wsum + 1e-30f);
    if (deg == 0) { mxx = 0.f; mxy = 0.f; mxz = 0.f; mxw = 0.f; }

    float4* agg4 = reinterpret_cast<float4*>(g_agg);
    size_t b = (size_t)node * 96 + lane;
    agg4[b]      = make_float4(sx * invd, sy * invd, sz * invd, sw * invd);
    agg4[b + 32] = make_float4(mxx, mxy, mxz, mxw);
    agg4[b + 64] = make_float4(dx * invw, dy * invw, dz * invw, dw * invw);
}

// ---------------- kernel 6: tf32 GEMM  Y[:,128g:128g+128] = agg @ W[384g:384g+384,:]
#define GTM 128
#define GTK 32

__global__ __launch_bounds__(256) void k_gemm(const float* __restrict__ Wg) {
    __shared__ float As[GTM][GTK + 4];   // stride 36
    __shared__ float Bs[GTK][D + 4];     // stride 132
    int tid = threadIdx.x;
    int wid = tid >> 5;
    int lane = tid & 31;
    int t = lane & 3;
    int g = lane >> 2;
    int wr = wid & 3;   // warp row: rows 32*wr
    int wc = wid >> 2;  // warp col: cols 64*wc
    int rowBlock = blockIdx.x * GTM;
    const float* Wp = Wg + (size_t)blockIdx.y * 384 * D;  // column-group rows of W

    float c[2][8][4];
#pragma unroll
    for (int i = 0; i < 2; i++)
#pragma unroll
        for (int jn = 0; jn < 8; jn++)
#pragma unroll
            for (int k = 0; k < 4; k++) c[i][jn][k] = 0.f;

    for (int kc = 0; kc < 384; kc += GTK) {
        // A chunk: 128 x 32
#pragma unroll
        for (int i = 0; i < 4; i++) {
            int idx = tid + 256 * i;
            int r = idx >> 3;
            int c4 = (idx & 7) * 4;
            float4 v = make_float4(0.f, 0.f, 0.f, 0.f);
            int grow = rowBlock + r;
            if (grow < NN)
                v = *(const float4*)(g_agg + (size_t)grow * DAGG + kc + c4);
            As[r][c4 + 0] = __uint_as_float(f2tf32(v.x));
            As[r][c4 + 1] = __uint_as_float(f2tf32(v.y));
            As[r][c4 + 2] = __uint_as_float(f2tf32(v.z));
            As[r][c4 + 3] = __uint_as_float(f2tf32(v.w));
        }
        // B chunk: 32 x 128
#pragma unroll
        for (int i = 0; i < 4; i++) {
            int idx = tid + 256 * i;
            int r = idx >> 5;
            int c4 = (idx & 31) * 4;
            float4 v = *(const float4*)(Wp + (size_t)(kc + r) * D + c4);
            Bs[r][c4 + 0] = __uint_as_float(f2tf32(v.x));
            Bs[r][c4 + 1] = __uint_as_float(f2tf32(v.y));
            Bs[r][c4 + 2] = __uint_as_float(f2tf32(v.z));
            Bs[r][c4 + 3] = __uint_as_float(f2tf32(v.w));
        }
        __syncthreads();
#pragma unroll
        for (int ks = 0; ks < GTK; ks += 8) {
            uint32_t a[2][4];
#pragma unroll
            for (int mt = 0; mt < 2; mt++) {
                int r0 = wr * 32 + mt * 16 + g;
                a[mt][0] = __float_as_uint(As[r0][ks + t]);
                a[mt][1] = __float_as_uint(As[r0 + 8][ks + t]);
                a[mt][2] = __float_as_uint(As[r0][ks + t + 4]);
                a[mt][3] = __float_as_uint(As[r0 + 8][ks + t + 4]);
            }
#pragma unroll
            for (int nt = 0; nt < 8; nt++) {
                int col = wc * 64 + nt * 8 + g;
                uint32_t b0 = __float_as_uint(Bs[ks + t][col]);
                uint32_t b1 = __float_as_uint(Bs[ks + t + 4][col]);
                mma_tf32(c[0][nt], a[0], b0, b1);
                mma_tf32(c[1][nt], a[1], b0, b1);
            }
        }
        __syncthreads();
    }
    // store Y
#pragma unroll
    for (int mt = 0; mt < 2; mt++) {
#pragma unroll
        for (int nt = 0; nt < 8; nt++) {
            int r0 = rowBlock + wr * 32 + mt * 16 + g;
            int col = wc * 64 + nt * 8 + 2 * t;
            size_t cb = (size_t)blockIdx.y * D + col;
            if (r0 < NN) {
                float2 v = make_float2(c[mt][nt][0], c[mt][nt][1]);
                *(float2*)(g_Y + (size_t)r0 * DAGG + cb) = v;
            }
            if (r0 + 8 < NN) {
                float2 v = make_float2(c[mt][nt][2], c[mt][nt][3]);
                *(float2*)(g_Y + (size_t)(r0 + 8) * DAGG + cb) = v;
            }
        }
    }
}

// ---------------- kernel 7: epilogue ----------------------------------------
__global__ void k_epi(const float* __restrict__ h, const float* __restrict__ snorm,
                      const float* __restrict__ bias, const float* __restrict__ gamma,
                      const float* __restrict__ beta, const float* __restrict__ mean,
                      const float* __restrict__ var, float* __restrict__ out) {
    int n = blockIdx.x;
    int j = threadIdx.x;
    int deg = g_off[n + 1] - g_off[n];
    float logD = logf((float)deg + 1.0f);
    float amp = logD * (1.0f / AVG_D_LOG_F);
    float att = AVG_D_LOG_F / fmaxf(logD, 1e-6f);
    size_t yb = (size_t)n * DAGG;
    float v = g_Y[yb + j] + amp * g_Y[yb + 128 + j] + att * g_Y[yb + 256 + j] + bias[j];
    v *= snorm[n];
    v = (v - mean[j]) * rsqrtf(var[j] + 1e-5f) * gamma[j] + beta[j];
    v = fmaxf(v, 0.f);
    out[(size_t)n * D + j] = h[(size_t)n * D + j] + v;
}

// ---------------- launch ----------------------------------------------------
extern "C" void kernel_launch(void* const* d_in, const int* in_sizes, int n_in,
                              void* d_out, int out_size) {
    const float* h = (const float*)d_in[0];
    const float* eig = (const float*)d_in[1];
    const float* snorm = (const float*)d_in[2];
    const float* W = (const float*)d_in[3];
    const float* bias = (const float*)d_in[4];
    const float* gamma = (const float*)d_in[5];
    const float* beta = (const float*)d_in[6];
    const float* mean = (const float*)d_in[7];
    const float* var = (const float*)d_in[8];
    const int* esrc = (const int*)d_in[9];
    const int* edst = (const int*)d_in[10];
    float* out = (float*)d_out;

    k_init<<<(NN + 255) / 256, 256>>>();
    k_deg<<<(EE + 255) / 256, 256>>>(edst);
    k_scan<<<1, 1024>>>();
    k_fill<<<(EE + 255) / 256, 256>>>(esrc, edst, eig);
    k_reduce<<<(NN + 7) / 8, 256>>>((const float4*)h);
    k_gemm<<<dim3((NN + GTM - 1) / GTM, 3), 256>>>(W);
    k_epi<<<NN, D>>>(h, snorm, bias, gamma, beta, mean, var, out);
}

// round 2
// speedup vs baseline: 1.4062x; 1.4062x over previous
#include <cuda_runtime.h>
#include <cuda_fp16.h>
#include <math.h>
#include <stdint.h>

#define NN 50000
#define EE 1600000
#define D 128
#define DAGG 384
#define CAP 128
#define AVG_D_LOG_F 3.4965075614664802f

// ---------------- static scratch --------------------------------------------
__device__ int g_cnt[NN];
__device__ int g_srcl[(size_t)NN * CAP];
__device__ float g_e1[NN];
__device__ __align__(16) __half g_hh[(size_t)NN * D];     // h in fp16
__device__ __align__(16) float g_agg[(size_t)NN * DAGG];  // [N,384] fp32

// ---------------- helpers ---------------------------------------------------
__device__ __forceinline__ uint32_t f2tf32(float f) {
    uint32_t r;
    asm("cvt.rna.tf32.f32 %0, %1;" : "=r"(r) : "f"(f));
    return r;
}

__device__ __forceinline__ void mma_tf32(float* c, const uint32_t* a,
                                         uint32_t b0, uint32_t b1) {
    asm volatile(
        "mma.sync.aligned.m16n8k8.row.col.f32.tf32.tf32.f32 "
        "{%0,%1,%2,%3}, {%4,%5,%6,%7}, {%8,%9}, {%0,%1,%2,%3};\n"
        : "+f"(c[0]), "+f"(c[1]), "+f"(c[2]), "+f"(c[3])
        : "r"(a[0]), "r"(a[1]), "r"(a[2]), "r"(a[3]), "r"(b0), "r"(b1));
}

__device__ __forceinline__ float4 h4conv(uint2 u) {
    __half2 a = *reinterpret_cast<__half2*>(&u.x);
    __half2 b = *reinterpret_cast<__half2*>(&u.y);
    float2 fa = __half22float2(a);
    float2 fb = __half22float2(b);
    return make_float4(fa.x, fa.y, fb.x, fb.y);
}

// ---------------- kernel 1: prep (h->fp16, zero counters, pack eig col0) ----
__global__ void k_prep(const float2* __restrict__ h2in, const float* __restrict__ eig) {
    int idx = blockIdx.x * blockDim.x + threadIdx.x;
    if (idx < NN * 64) {
        float2 v = h2in[idx];
        reinterpret_cast<__half2*>(g_hh)[idx] = __floats2half2_rn(v.x, v.y);
    }
    if (idx < NN) {
        g_cnt[idx] = 0;
        g_e1[idx] = eig[(size_t)idx * 4];
    }
}

// ---------------- kernel 2: bucket fill --------------------------------------
__global__ void k_fill(const int* __restrict__ src, const int* __restrict__ dst) {
    int i = blockIdx.x * blockDim.x + threadIdx.x;
    if (i >= EE) return;
    int d = dst[i];
    int pos = atomicAdd(&g_cnt[d], 1);
    g_srcl[(size_t)d * CAP + pos] = src[i];
}

// ---------------- kernel 3: warp-per-node multi-aggregator reduce ------------
__global__ __launch_bounds__(256) void k_reduce() {
    int wid = threadIdx.x >> 5;
    int lane = threadIdx.x & 31;
    int node = blockIdx.x * 8 + wid;
    if (node >= NN) return;
    int deg = g_cnt[node];
    size_t base = (size_t)node * CAP;
    float e1d = g_e1[node];
    const uint2* h2 = reinterpret_cast<const uint2*>(g_hh);  // row stride 32

    float sx = 0.f, sy = 0.f, sz = 0.f, sw = 0.f;
    float mxx = -3.402823466e38f, mxy = mxx, mxz = mxx, mxw = mxx;
    float dx = 0.f, dy = 0.f, dz = 0.f, dw = 0.f;
    float wsum = 0.f;

    int j = 0;
    for (; j + 2 <= deg; j += 2) {
        int s0 = g_srcl[base + j];
        int s1 = g_srcl[base + j + 1];
        float w0 = fabsf(g_e1[s0] - e1d);
        float w1 = fabsf(g_e1[s1] - e1d);
        uint2 u0 = h2[(size_t)s0 * 32 + lane];
        uint2 u1 = h2[(size_t)s1 * 32 + lane];
        float4 v0 = h4conv(u0);
        float4 v1 = h4conv(u1);
        sx += v0.x; sy += v0.y; sz += v0.z; sw += v0.w;
        mxx = fmaxf(mxx, v0.x); mxy = fmaxf(mxy, v0.y);
        mxz = fmaxf(mxz, v0.z); mxw = fmaxf(mxw, v0.w);
        dx = fmaf(w0, v0.x, dx); dy = fmaf(w0, v0.y, dy);
        dz = fmaf(w0, v0.z, dz); dw = fmaf(w0, v0.w, dw);
        wsum += w0;
        sx += v1.x; sy += v1.y; sz += v1.z; sw += v1.w;
        mxx = fmaxf(mxx, v1.x); mxy = fmaxf(mxy, v1.y);
        mxz = fmaxf(mxz, v1.z); mxw = fmaxf(mxw, v1.w);
        dx = fmaf(w1, v1.x, dx); dy = fmaf(w1, v1.y, dy);
        dz = fmaf(w1, v1.z, dz); dw = fmaf(w1, v1.w, dw);
        wsum += w1;
    }
    if (j < deg) {
        int s0 = g_srcl[base + j];
        float w0 = fabsf(g_e1[s0] - e1d);
        float4 v0 = h4conv(h2[(size_t)s0 * 32 + lane]);
        sx += v0.x; sy += v0.y; sz += v0.z; sw += v0.w;
        mxx = fmaxf(mxx, v0.x); mxy = fmaxf(mxy, v0.y);
        mxz = fmaxf(mxz, v0.z); mxw = fmaxf(mxw, v0.w);
        dx = fmaf(w0, v0.x, dx); dy = fmaf(w0, v0.y, dy);
        dz = fmaf(w0, v0.z, dz); dw = fmaf(w0, v0.w, dw);
        wsum += w0;
    }

    float invd = 1.f / (float)(deg > 0 ? deg : 1);
    float invw = 1.f / (wsum + 1e-30f);
    if (deg == 0) { mxx = 0.f; mxy = 0.f; mxz = 0.f; mxw = 0.f; }

    float4* agg4 = reinterpret_cast<float4*>(g_agg);
    size_t b = (size_t)node * 96 + lane;
    agg4[b]      = make_float4(sx * invd, sy * invd, sz * invd, sw * invd);
    agg4[b + 32] = make_float4(mxx, mxy, mxz, mxw);
    agg4[b + 64] = make_float4(dx * invw, dy * invw, dz * invw, dw * invw);
}

// ---------------- kernel 4: fused tf32 GEMM (K=1152) + full epilogue ---------
#define GTM 128
#define GTK 32

__global__ __launch_bounds__(256) void k_gemm(
    const float* __restrict__ W, const float* __restrict__ h,
    const float* __restrict__ snorm, const float* __restrict__ bias,
    const float* __restrict__ gamma, const float* __restrict__ beta,
    const float* __restrict__ mean, const float* __restrict__ var,
    float* __restrict__ out) {
    __shared__ float As[GTM][GTK + 4];
    __shared__ float Bs[GTK][D + 4];
    __shared__ float scoef[2][GTM];  // amp, att per tile row
    __shared__ float ssn[GTM];       // snorm per tile row
    int tid = threadIdx.x;
    int wid = tid >> 5;
    int lane = tid & 31;
    int t = lane & 3;
    int g = lane >> 2;
    int wr = wid & 3;
    int wc = wid >> 2;
    int rowBlock = blockIdx.x * GTM;

    for (int i = tid; i < GTM; i += 256) {
        int r = rowBlock + i;
        float amp = 0.f, att = 0.f, sn = 0.f;
        if (r < NN) {
            int deg = g_cnt[r];
            float logD = logf((float)deg + 1.0f);
            amp = logD * (1.0f / AVG_D_LOG_F);
            att = AVG_D_LOG_F / fmaxf(logD, 1e-6f);
            sn = snorm[r];
        }
        scoef[0][i] = amp;
        scoef[1][i] = att;
        ssn[i] = sn;
    }
    __syncthreads();

    float c[2][8][4];
#pragma unroll
    for (int i = 0; i < 2; i++)
#pragma unroll
        for (int jn = 0; jn < 8; jn++)
#pragma unroll
            for (int k = 0; k < 4; k++) c[i][jn][k] = 0.f;

    for (int kc = 0; kc < 3 * DAGG; kc += GTK) {
        int grp = kc / DAGG;
        int k0 = kc - grp * DAGG;
        // A: 128 x 32 with per-row scaler folded in
#pragma unroll
        for (int i = 0; i < 4; i++) {
            int idx = tid + 256 * i;
            int r = idx >> 3;
            int c4 = (idx & 7) * 4;
            float coef = (grp == 0) ? 1.0f : scoef[grp - 1][r];
            float4 v = make_float4(0.f, 0.f, 0.f, 0.f);
            int grow = rowBlock + r;
            if (grow < NN)
                v = *(const float4*)(g_agg + (size_t)grow * DAGG + k0 + c4);
            As[r][c4 + 0] = __uint_as_float(f2tf32(v.x * coef));
            As[r][c4 + 1] = __uint_as_float(f2tf32(v.y * coef));
            As[r][c4 + 2] = __uint_as_float(f2tf32(v.z * coef));
            As[r][c4 + 3] = __uint_as_float(f2tf32(v.w * coef));
        }
        // B: 32 x 128 from W[1152,128]
#pragma unroll
        for (int i = 0; i < 4; i++) {
            int idx = tid + 256 * i;
            int r = idx >> 5;
            int c4 = (idx & 31) * 4;
            float4 v = *(const float4*)(W + (size_t)(kc + r) * D + c4);
            Bs[r][c4 + 0] = __uint_as_float(f2tf32(v.x));
            Bs[r][c4 + 1] = __uint_as_float(f2tf32(v.y));
            Bs[r][c4 + 2] = __uint_as_float(f2tf32(v.z));
            Bs[r][c4 + 3] = __uint_as_float(f2tf32(v.w));
        }
        __syncthreads();
#pragma unroll
        for (int ks = 0; ks < GTK; ks += 8) {
            uint32_t a[2][4];
#pragma unroll
            for (int mt = 0; mt < 2; mt++) {
                int r0 = wr * 32 + mt * 16 + g;
                a[mt][0] = __float_as_uint(As[r0][ks + t]);
                a[mt][1] = __float_as_uint(As[r0 + 8][ks + t]);
                a[mt][2] = __float_as_uint(As[r0][ks + t + 4]);
                a[mt][3] = __float_as_uint(As[r0 + 8][ks + t + 4]);
            }
#pragma unroll
            for (int nt = 0; nt < 8; nt++) {
                int col = wc * 64 + nt * 8 + g;
                uint32_t b0 = __float_as_uint(Bs[ks + t][col]);
                uint32_t b1 = __float_as_uint(Bs[ks + t + 4][col]);
                mma_tf32(c[0][nt], a[0], b0, b1);
                mma_tf32(c[1][nt], a[1], b0, b1);
            }
        }
        __syncthreads();
    }

    // fused epilogue: bias -> graphnorm -> BN -> relu -> residual -> out
#pragma unroll
    for (int nt = 0; nt < 8; nt++) {
        int col = wc * 64 + nt * 8 + 2 * t;
        float2 bi = *(const float2*)(bias + col);
        float2 mn = *(const float2*)(mean + col);
        float2 vr = *(const float2*)(var + col);
        float2 gm = *(const float2*)(gamma + col);
        float2 bt = *(const float2*)(beta + col);
        float sc0 = rsqrtf(vr.x + 1e-5f) * gm.x;
        float sc1 = rsqrtf(vr.y + 1e-5f) * gm.y;
        float sh0 = bt.x - mn.x * sc0;
        float sh1 = bt.y - mn.y * sc1;
#pragma unroll
        for (int mt = 0; mt < 2; mt++) {
            int rl = wr * 32 + mt * 16 + g;
#pragma unroll
            for (int p = 0; p < 2; p++) {
                int rloc = rl + p * 8;
                int r = rowBlock + rloc;
                if (r < NN) {
                    float sn = ssn[rloc];
                    float v0 = (c[mt][nt][p * 2 + 0] + bi.x) * sn;
                    float v1 = (c[mt][nt][p * 2 + 1] + bi.y) * sn;
                    v0 = fmaxf(fmaf(v0, sc0, sh0), 0.f);
                    v1 = fmaxf(fmaf(v1, sc1, sh1), 0.f);
                    float2 hres = *(const float2*)(h + (size_t)r * D + col);
                    float2 o = make_float2(hres.x + v0, hres.y + v1);
                    *(float2*)(out + (size_t)r * D + col) = o;
                }
            }
        }
    }
}

// ---------------- launch ----------------------------------------------------
extern "C" void kernel_launch(void* const* d_in, const int* in_sizes, int n_in,
                              void* d_out, int out_size) {
    const float* h = (const float*)d_in[0];
    const float* eig = (const float*)d_in[1];
    const float* snorm = (const float*)d_in[2];
    const float* W = (const float*)d_in[3];
    const float* bias = (const float*)d_in[4];
    const float* gamma = (const float*)d_in[5];
    const float* beta = (const float*)d_in[6];
    const float* mean = (const float*)d_in[7];
    const float* var = (const float*)d_in[8];
    const int* esrc = (const int*)d_in[9];
    const int* edst = (const int*)d_in[10];
    float* out = (float*)d_out;

    k_prep<<<(NN * 64 + 255) / 256, 256>>>((const float2*)h, eig);
    k_fill<<<(EE + 255) / 256, 256>>>(esrc, edst);
    k_reduce<<<(NN + 7) / 8, 256>>>();
    k_gemm<<<(NN + GTM - 1) / GTM, 256>>>(W, h, snorm, bias, gamma, beta, mean, var, out);
}

// round 3
// speedup vs baseline: 1.9861x; 1.4124x over previous
#include <cuda_runtime.h>
#include <cuda_fp16.h>
#include <math.h>
#include <stdint.h>

#define NN 50000
#define EE 1600000
#define D 128
#define DAGG 384
#define DCAT 1152
#define CAP 128
#define AVG_D_LOG_F 3.4965075614664802f

// ---------------- static scratch --------------------------------------------
__device__ int g_cnt[NN];
__device__ int g_srcl[(size_t)NN * CAP];
__device__ float g_e1[NN];
__device__ __align__(16) __half g_hh[(size_t)NN * D];        // h in fp16
__device__ __align__(16) __half g_aggh[(size_t)NN * DCAT];   // prescaled hcat fp16
__device__ __align__(16) __half g_Wh[(size_t)DCAT * D];      // W in fp16

// ---------------- helpers ---------------------------------------------------
__device__ __forceinline__ float4 h4conv(uint2 u) {
    __half2 a = *reinterpret_cast<__half2*>(&u.x);
    __half2 b = *reinterpret_cast<__half2*>(&u.y);
    float2 fa = __half22float2(a);
    float2 fb = __half22float2(b);
    return make_float4(fa.x, fa.y, fb.x, fb.y);
}

__device__ __forceinline__ uint2 pack4(float4 v) {
    uint2 r;
    __half2 lo = __floats2half2_rn(v.x, v.y);
    __half2 hi = __floats2half2_rn(v.z, v.w);
    r.x = *reinterpret_cast<uint32_t*>(&lo);
    r.y = *reinterpret_cast<uint32_t*>(&hi);
    return r;
}

__device__ __forceinline__ void mma_f16(float* c, const uint32_t* a,
                                        uint32_t b0, uint32_t b1) {
    asm volatile(
        "mma.sync.aligned.m16n8k16.row.col.f32.f16.f16.f32 "
        "{%0,%1,%2,%3}, {%4,%5,%6,%7}, {%8,%9}, {%0,%1,%2,%3};\n"
        : "+f"(c[0]), "+f"(c[1]), "+f"(c[2]), "+f"(c[3])
        : "r"(a[0]), "r"(a[1]), "r"(a[2]), "r"(a[3]), "r"(b0), "r"(b1));
}

__device__ __forceinline__ void ldm_x4(uint32_t* r, uint32_t addr) {
    asm volatile("ldmatrix.sync.aligned.m8n8.x4.shared.b16 {%0,%1,%2,%3}, [%4];"
                 : "=r"(r[0]), "=r"(r[1]), "=r"(r[2]), "=r"(r[3]) : "r"(addr));
}

__device__ __forceinline__ void ldm_x4t(uint32_t* r, uint32_t addr) {
    asm volatile("ldmatrix.sync.aligned.m8n8.x4.trans.shared.b16 {%0,%1,%2,%3}, [%4];"
                 : "=r"(r[0]), "=r"(r[1]), "=r"(r[2]), "=r"(r[3]) : "r"(addr));
}

__device__ __forceinline__ void cp16(uint32_t smem_addr, const void* gptr) {
    asm volatile("cp.async.cg.shared.global [%0], [%1], 16;\n"
                 :: "r"(smem_addr), "l"(gptr));
}

// ---------------- kernel 1: prep (h->fp16, W->fp16, counters, eig col0) -----
__global__ void k_prep(const float2* __restrict__ h2in, const float* __restrict__ eig,
                       const float2* __restrict__ W2) {
    int idx = blockIdx.x * blockDim.x + threadIdx.x;
    if (idx < NN * 64) {
        float2 v = h2in[idx];
        reinterpret_cast<__half2*>(g_hh)[idx] = __floats2half2_rn(v.x, v.y);
    }
    if (idx < DCAT * 64) {  // 73728 half2 of W
        float2 v = W2[idx];
        reinterpret_cast<__half2*>(g_Wh)[idx] = __floats2half2_rn(v.x, v.y);
    }
    if (idx < NN) {
        g_cnt[idx] = 0;
        g_e1[idx] = eig[(size_t)idx * 4];
    }
}

// ---------------- kernel 2: bucket fill (4 edges/thread) ---------------------
__global__ void k_fill(const int4* __restrict__ src4, const int4* __restrict__ dst4) {
    int i = blockIdx.x * blockDim.x + threadIdx.x;
    if (i >= EE / 4) return;
    int4 d = dst4[i];
    int4 s = src4[i];
    int p0 = atomicAdd(&g_cnt[d.x], 1);
    int p1 = atomicAdd(&g_cnt[d.y], 1);
    int p2 = atomicAdd(&g_cnt[d.z], 1);
    int p3 = atomicAdd(&g_cnt[d.w], 1);
    g_srcl[(size_t)d.x * CAP + p0] = s.x;
    g_srcl[(size_t)d.y * CAP + p1] = s.y;
    g_srcl[(size_t)d.z * CAP + p2] = s.z;
    g_srcl[(size_t)d.w * CAP + p3] = s.w;
}

// ---------------- kernel 3: warp-per-node reduce, writes prescaled fp16 -----
__global__ __launch_bounds__(256) void k_reduce() {
    int wid = threadIdx.x >> 5;
    int lane = threadIdx.x & 31;
    int node = blockIdx.x * 8 + wid;
    if (node >= NN) return;
    int deg = g_cnt[node];
    size_t base = (size_t)node * CAP;
    float e1d = g_e1[node];
    const uint2* h2 = reinterpret_cast<const uint2*>(g_hh);  // row stride 32

    float sx = 0.f, sy = 0.f, sz = 0.f, sw = 0.f;
    float mxx = -3.402823466e38f, mxy = mxx, mxz = mxx, mxw = mxx;
    float dx = 0.f, dy = 0.f, dz = 0.f, dw = 0.f;
    float wsum = 0.f;

    int j = 0;
    for (; j + 2 <= deg; j += 2) {
        int s0 = g_srcl[base + j];
        int s1 = g_srcl[base + j + 1];
        float w0 = fabsf(g_e1[s0] - e1d);
        float w1 = fabsf(g_e1[s1] - e1d);
        float4 v0 = h4conv(h2[(size_t)s0 * 32 + lane]);
        float4 v1 = h4conv(h2[(size_t)s1 * 32 + lane]);
        sx += v0.x; sy += v0.y; sz += v0.z; sw += v0.w;
        mxx = fmaxf(mxx, v0.x); mxy = fmaxf(mxy, v0.y);
        mxz = fmaxf(mxz, v0.z); mxw = fmaxf(mxw, v0.w);
        dx = fmaf(w0, v0.x, dx); dy = fmaf(w0, v0.y, dy);
        dz = fmaf(w0, v0.z, dz); dw = fmaf(w0, v0.w, dw);
        wsum += w0;
        sx += v1.x; sy += v1.y; sz += v1.z; sw += v1.w;
        mxx = fmaxf(mxx, v1.x); mxy = fmaxf(mxy, v1.y);
        mxz = fmaxf(mxz, v1.z); mxw = fmaxf(mxw, v1.w);
        dx = fmaf(w1, v1.x, dx); dy = fmaf(w1, v1.y, dy);
        dz = fmaf(w1, v1.z, dz); dw = fmaf(w1, v1.w, dw);
        wsum += w1;
    }
    if (j < deg) {
        int s0 = g_srcl[base + j];
        float w0 = fabsf(g_e1[s0] - e1d);
        float4 v0 = h4conv(h2[(size_t)s0 * 32 + lane]);
        sx += v0.x; sy += v0.y; sz += v0.z; sw += v0.w;
        mxx = fmaxf(mxx, v0.x); mxy = fmaxf(mxy, v0.y);
        mxz = fmaxf(mxz, v0.z); mxw = fmaxf(mxw, v0.w);
        dx = fmaf(w0, v0.x, dx); dy = fmaf(w0, v0.y, dy);
        dz = fmaf(w0, v0.z, dz); dw = fmaf(w0, v0.w, dw);
        wsum += w0;
    }

    float invd = 1.f / (float)(deg > 0 ? deg : 1);
    float invw = 1.f / (wsum + 1e-30f);
    if (deg == 0) { mxx = 0.f; mxy = 0.f; mxz = 0.f; mxw = 0.f; }

    float logD = logf((float)deg + 1.0f);
    float ampc = logD * (1.0f / AVG_D_LOG_F);
    float attc = AVG_D_LOG_F / fmaxf(logD, 1e-6f);

    float4 me = make_float4(sx * invd, sy * invd, sz * invd, sw * invd);
    float4 mx = make_float4(mxx, mxy, mxz, mxw);
    float4 dv = make_float4(dx * invw, dy * invw, dz * invw, dw * invw);

    uint2* o = reinterpret_cast<uint2*>(g_aggh) + (size_t)node * 288;
    // scaler 0: identity
    o[lane]       = pack4(me);
    o[32 + lane]  = pack4(mx);
    o[64 + lane]  = pack4(dv);
    // scaler 1: amplification
    o[96 + lane]  = pack4(make_float4(me.x * ampc, me.y * ampc, me.z * ampc, me.w * ampc));
    o[128 + lane] = pack4(make_float4(mx.x * ampc, mx.y * ampc, mx.z * ampc, mx.w * ampc));
    o[160 + lane] = pack4(make_float4(dv.x * ampc, dv.y * ampc, dv.z * ampc, dv.w * ampc));
    // scaler 2: attenuation
    o[192 + lane] = pack4(make_float4(me.x * attc, me.y * attc, me.z * attc, me.w * attc));
    o[224 + lane] = pack4(make_float4(mx.x * attc, mx.y * attc, mx.z * attc, mx.w * attc));
    o[256 + lane] = pack4(make_float4(dv.x * attc, dv.y * attc, dv.z * attc, dv.w * attc));
}

// ---------------- kernel 4: fp16 GEMM (ldmatrix + mma.m16n8k16) + epilogue ---
#define BM 64
#define BN 128
#define BK 32
#define NKT (DCAT / BK)  // 36

__global__ __launch_bounds__(256) void k_gemm(
    const float* __restrict__ h, const float* __restrict__ snorm,
    const float* __restrict__ bias, const float* __restrict__ gamma,
    const float* __restrict__ beta, const float* __restrict__ mean,
    const float* __restrict__ var, float* __restrict__ out) {
    __shared__ __half As[2][BM][40];    // stride 80B (conflict-free ldmatrix)
    __shared__ __half Bs[2][BK][136];   // stride 272B
    __shared__ float ssn[BM];

    int tid = threadIdx.x;
    int wid = tid >> 5;
    int lane = tid & 31;
    int t = lane & 3;
    int g = lane >> 2;
    int wr = wid >> 2;  // 0..1 : rows wr*32
    int wc = wid & 3;   // 0..3 : cols wc*32
    int rowBlock = blockIdx.x * BM;

    if (tid < BM) {
        int r = rowBlock + tid;
        ssn[tid] = (r < NN) ? snorm[r] : 0.f;
    }

    // A loads: 256 chunks of 16B (64 rows x 4 chunks); 1 per thread
    int a_row = tid >> 2, a_chk = tid & 3;
    int a_grow = rowBlock + a_row; if (a_grow > NN - 1) a_grow = NN - 1;
    const __half* a_src = g_aggh + (size_t)a_grow * DCAT + a_chk * 8;
    uint32_t a_dst0 = (uint32_t)__cvta_generic_to_shared(&As[0][a_row][a_chk * 8]);
    uint32_t a_dst1 = (uint32_t)__cvta_generic_to_shared(&As[1][a_row][a_chk * 8]);

    // B loads: 512 chunks (32 rows x 16 chunks); 2 per thread
    int b_row0 = tid >> 4, b_col = tid & 15;        // rows 0..15
    int b_row1 = b_row0 + 16;                        // rows 16..31
    const __half* b_src0 = g_Wh + (size_t)b_row0 * D + b_col * 8;
    const __half* b_src1 = g_Wh + (size_t)b_row1 * D + b_col * 8;
    uint32_t b_dst00 = (uint32_t)__cvta_generic_to_shared(&Bs[0][b_row0][b_col * 8]);
    uint32_t b_dst01 = (uint32_t)__cvta_generic_to_shared(&Bs[0][b_row1][b_col * 8]);
    uint32_t b_dst10 = (uint32_t)__cvta_generic_to_shared(&Bs[1][b_row0][b_col * 8]);
    uint32_t b_dst11 = (uint32_t)__cvta_generic_to_shared(&Bs[1][b_row1][b_col * 8]);

    float c[2][4][4];
#pragma unroll
    for (int mt = 0; mt < 2; mt++)
#pragma unroll
        for (int nt = 0; nt < 4; nt++)
#pragma unroll
            for (int k = 0; k < 4; k++) c[mt][nt][k] = 0.f;

    // prefetch tile 0
    cp16(a_dst0, a_src);
    cp16(b_dst00, b_src0);
    cp16(b_dst01, b_src1);
    asm volatile("cp.async.commit_group;\n");

    // ldmatrix source addresses (per buf)
    uint32_t a_lm[2], b_lm[2];
#pragma unroll
    for (int buf = 0; buf < 2; buf++) {
        a_lm[buf] = (uint32_t)__cvta_generic_to_shared(
            &As[buf][wr * 32 + (lane & 15)][(lane >> 4) << 3]);
        b_lm[buf] = (uint32_t)__cvta_generic_to_shared(
            &Bs[buf][lane & 15][wc * 32 + ((lane >> 4) << 3)]);
    }

    for (int kt = 0; kt < NKT; kt++) {
        int buf = kt & 1;
        if (kt + 1 < NKT) {
            size_t koff = (size_t)(kt + 1) * BK;
            cp16(buf ? a_dst0 : a_dst1, a_src + koff);
            cp16(buf ? b_dst00 : b_dst10, b_src0 + koff * D);
            cp16(buf ? b_dst01 : b_dst11, b_src1 + koff * D);
            asm volatile("cp.async.commit_group;\n");
            asm volatile("cp.async.wait_group 1;\n");
        } else {
            asm volatile("cp.async.wait_group 0;\n");
        }
        __syncthreads();

#pragma unroll
        for (int ks = 0; ks < 2; ks++) {
            uint32_t a[2][4];
            ldm_x4(a[0], a_lm[buf] + ks * 32);            // +16 halfs
            ldm_x4(a[1], a_lm[buf] + 16 * 80 + ks * 32);  // +16 rows
            uint32_t b[2][4];
            ldm_x4t(b[0], b_lm[buf] + ks * 16 * 272);
            ldm_x4t(b[1], b_lm[buf] + ks * 16 * 272 + 32);  // +16 cols
#pragma unroll
            for (int mt = 0; mt < 2; mt++) {
                mma_f16(c[mt][0], a[mt], b[0][0], b[0][1]);
                mma_f16(c[mt][1], a[mt], b[0][2], b[0][3]);
                mma_f16(c[mt][2], a[mt], b[1][0], b[1][1]);
                mma_f16(c[mt][3], a[mt], b[1][2], b[1][3]);
            }
        }
        __syncthreads();
    }

    // fused epilogue
#pragma unroll
    for (int nt = 0; nt < 4; nt++) {
        int col = wc * 32 + nt * 8 + 2 * t;
        float2 bi = *(const float2*)(bias + col);
        float2 mn = *(const float2*)(mean + col);
        float2 vr = *(const float2*)(var + col);
        float2 gm = *(const float2*)(gamma + col);
        float2 bt = *(const float2*)(beta + col);
        float sc0 = rsqrtf(vr.x + 1e-5f) * gm.x;
        float sc1 = rsqrtf(vr.y + 1e-5f) * gm.y;
        float sh0 = bt.x - mn.x * sc0;
        float sh1 = bt.y - mn.y * sc1;
#pragma unroll
        for (int mt = 0; mt < 2; mt++) {
#pragma unroll
            for (int p = 0; p < 2; p++) {
                int rloc = wr * 32 + mt * 16 + g + p * 8;
                int r = rowBlock + rloc;
                if (r < NN) {
                    float sn = ssn[rloc];
                    float v0 = (c[mt][nt][p * 2 + 0] + bi.x) * sn;
                    float v1 = (c[mt][nt][p * 2 + 1] + bi.y) * sn;
                    v0 = fmaxf(fmaf(v0, sc0, sh0), 0.f);
                    v1 = fmaxf(fmaf(v1, sc1, sh1), 0.f);
                    float2 hres = *(const float2*)(h + (size_t)r * D + col);
                    *(float2*)(out + (size_t)r * D + col) =
                        make_float2(hres.x + v0, hres.y + v1);
                }
            }
        }
    }
}

// ---------------- launch ----------------------------------------------------
extern "C" void kernel_launch(void* const* d_in, const int* in_sizes, int n_in,
                              void* d_out, int out_size) {
    const float* h = (const float*)d_in[0];
    const float* eig = (const float*)d_in[1];
    const float* snorm = (const float*)d_in[2];
    const float* W = (const float*)d_in[3];
    const float* bias = (const float*)d_in[4];
    const float* gamma = (const float*)d_in[5];
    const float* beta = (const float*)d_in[6];
    const float* mean = (const float*)d_in[7];
    const float* var = (const float*)d_in[8];
    const int* esrc = (const int*)d_in[9];
    const int* edst = (const int*)d_in[10];
    float* out = (float*)d_out;

    k_prep<<<(NN * 64 + 255) / 256, 256>>>((const float2*)h, eig, (const float2*)W);
    k_fill<<<(EE / 4 + 255) / 256, 256>>>((const int4*)esrc, (const int4*)edst);
    k_reduce<<<(NN + 7) / 8, 256>>>();
    k_gemm<<<(NN + BM - 1) / BM, 256>>>(h, snorm, bias, gamma, beta, mean, var, out);
}